// round 1
// baseline (speedup 1.0000x reference)
#include <cuda_runtime.h>
#include <math.h>

// ---------------- problem constants ----------------
#define NB    16          // batch
#define NCH   5           // channels
#define HIMG  256
#define WIMG  256
#define PP    8           // patch
#define SEQ   1024        // tokens per image (32*32)
#define NT    16384       // total tokens NB*SEQ
#define PD    320         // C*P*P
#define SF    64
#define ED    128
#define HS    512
#define NHD   4
#define HDIM  128
#define FF    2048
#define NE    6
#define NS    2
#define NLAY  4
#define NCLS  2

// ---------------- scratch (static device memory; no allocation allowed) ----------------
__device__ float g_t[NT * PD];
__device__ float g_z1[NT * SF];
__device__ float g_z[NT * ED];
__device__ float g_h[NT * HS];
__device__ float g_qkv[NT * 3 * HS];
__device__ float g_scores[(size_t)NB * NHD * SEQ * SEQ];   // 268 MB
__device__ float g_attno[NT * HS];
__device__ float g_a[NT * HS];
__device__ float g_spec[NT * HS];
__device__ float g_m[NT * HS];
__device__ float g_hid[NT * FF];                            // 134 MB
__device__ float g_sp[NT * NS];
__device__ int   g_eidx[NE * NT];
__device__ float g_ewt[NE * NT];
__device__ int   g_ecnt[NE];
__device__ float g_pool[NB * HS];

// ---------------- small helpers ----------------
__device__ __forceinline__ float warp_sum(float v) {
    #pragma unroll
    for (int o = 16; o; o >>= 1) v += __shfl_xor_sync(0xffffffffu, v, o);
    return v;
}
__device__ __forceinline__ float warp_max(float v) {
    #pragma unroll
    for (int o = 16; o; o >>= 1) v = fmaxf(v, __shfl_xor_sync(0xffffffffu, v, o));
    return v;
}

// ---------------- patch extraction ----------------
__global__ void patchify_kernel(const float* __restrict__ x) {
    int idx = blockIdx.x * blockDim.x + threadIdx.x;
    if (idx >= NT * PD) return;
    int n = idx / PD, f = idx % PD;
    int b = n / SEQ, s = n % SEQ;
    int sh = s >> 5, sw = s & 31;
    int c = f >> 6, r = f & 63;
    int pi = r >> 3, pj = r & 7;
    g_t[idx] = x[(((size_t)(b * NCH + c) * HIMG + (sh * PP + pi)) * WIMG) + (sw * PP + pj)];
}

// ---------------- positional encoding add ----------------
__global__ void add_pe_kernel() {
    int idx = blockIdx.x * blockDim.x + threadIdx.x;
    if (idx >= NT * ED) return;
    int n = idx >> 7, d = idx & 127;
    int s = n & (SEQ - 1);
    int i2 = d & ~1;
    float div = expf(-(float)i2 * (9.2103403719761836f / (float)ED));
    float arg = (float)s * div;
    float pe = (d & 1) ? cosf(arg) : sinf(arg);
    g_z[idx] += pe;
}

// ---------------- generic TN GEMM:  C[m,n] = act( sum_k A[m,k]*W[n,k] + bias[n] ) ----------------
// BM=BN=64, BK=32, 256 threads, 4x4 microtile.
// gidx: optional row gather on A. mcnt: optional dynamic row count (device).
// SCATTER: C[sidx[m]] += wv[m*ws] * (acc + bias[n])   (row-unique within a launch)
template<int ACT, int SCATTER>
__global__ __launch_bounds__(256) void gemm_tn(
    const float* __restrict__ A, const float* __restrict__ W,
    const float* __restrict__ bias, float* __restrict__ C,
    int M, int N, int K,
    const int* __restrict__ gidx, const int* __restrict__ mcnt,
    const int* __restrict__ sidx, const float* __restrict__ wv, int ws)
{
    int Mr = mcnt ? *mcnt : M;
    int m0 = blockIdx.y * 64;
    int n0 = blockIdx.x * 64;
    if (m0 >= Mr) return;

    __shared__ float As[32][64];
    __shared__ float Ws[32][64];
    __shared__ int   ridx[64];

    int tid = threadIdx.x;
    int tx = tid & 15, ty = tid >> 4;

    if (tid < 64) {
        int r = m0 + tid;
        if (r > Mr - 1) r = Mr - 1;
        ridx[tid] = gidx ? gidx[r] : r;
    }
    __syncthreads();

    float acc[4][4] = {};

    for (int kk = 0; kk < K; kk += 32) {
        #pragma unroll
        for (int i = 0; i < 2; i++) {
            int f = tid + i * 256;
            int r = f >> 3, c = (f & 7) * 4;
            float4 av = *(const float4*)&A[(size_t)ridx[r] * K + kk + c];
            As[c + 0][r] = av.x; As[c + 1][r] = av.y; As[c + 2][r] = av.z; As[c + 3][r] = av.w;
            float4 wv4 = *(const float4*)&W[(size_t)(n0 + r) * K + kk + c];
            Ws[c + 0][r] = wv4.x; Ws[c + 1][r] = wv4.y; Ws[c + 2][r] = wv4.z; Ws[c + 3][r] = wv4.w;
        }
        __syncthreads();
        #pragma unroll
        for (int k = 0; k < 32; k++) {
            float4 a4 = *(const float4*)&As[k][ty * 4];
            float4 b4 = *(const float4*)&Ws[k][tx * 4];
            float av[4] = {a4.x, a4.y, a4.z, a4.w};
            float bv[4] = {b4.x, b4.y, b4.z, b4.w};
            #pragma unroll
            for (int i = 0; i < 4; i++)
                #pragma unroll
                for (int j = 0; j < 4; j++)
                    acc[i][j] = fmaf(av[i], bv[j], acc[i][j]);
        }
        __syncthreads();
    }

    #pragma unroll
    for (int i = 0; i < 4; i++) {
        int m = m0 + ty * 4 + i;
        if (m >= Mr) break;
        if (SCATTER) {
            int row = sidx ? sidx[m] : m;
            float wgt = wv[(size_t)m * ws];
            float* crow = C + (size_t)row * N + n0 + tx * 4;
            #pragma unroll
            for (int j = 0; j < 4; j++) {
                int n = n0 + tx * 4 + j;
                crow[j] += wgt * (acc[i][j] + bias[n]);
            }
        } else {
            float* crow = C + (size_t)m * N + n0 + tx * 4;
            #pragma unroll
            for (int j = 0; j < 4; j++) {
                int n = n0 + tx * 4 + j;
                float v = acc[i][j] + bias[n];
                if (ACT == 1) v = fmaxf(v, 0.f);
                if (ACT == 2) v = 0.5f * v * (1.f + erff(v * 0.70710678118654752f));
                crow[j] = v;
            }
        }
    }
}

// ---------------- attention: scores = Q @ K^T (raw; scale applied in softmax) ----------------
__global__ __launch_bounds__(256) void attn_scores_kernel() {
    int z = blockIdx.z; int b = z >> 2; int h = z & 3;
    const float* Q  = g_qkv + (size_t)b * SEQ * (3 * HS) + h * HDIM;
    const float* Kp = Q + HS;
    float* Cs = g_scores + (size_t)z * SEQ * SEQ;
    int m0 = blockIdx.y * 64, n0 = blockIdx.x * 64;

    __shared__ float As[32][64];
    __shared__ float Ws[32][64];
    int tid = threadIdx.x;
    int tx = tid & 15, ty = tid >> 4;
    float acc[4][4] = {};

    for (int kk = 0; kk < HDIM; kk += 32) {
        #pragma unroll
        for (int i = 0; i < 2; i++) {
            int f = tid + i * 256;
            int r = f >> 3, c = (f & 7) * 4;
            float4 qa = *(const float4*)&Q[(size_t)(m0 + r) * (3 * HS) + kk + c];
            As[c + 0][r] = qa.x; As[c + 1][r] = qa.y; As[c + 2][r] = qa.z; As[c + 3][r] = qa.w;
            float4 ka = *(const float4*)&Kp[(size_t)(n0 + r) * (3 * HS) + kk + c];
            Ws[c + 0][r] = ka.x; Ws[c + 1][r] = ka.y; Ws[c + 2][r] = ka.z; Ws[c + 3][r] = ka.w;
        }
        __syncthreads();
        #pragma unroll
        for (int k = 0; k < 32; k++) {
            float4 a4 = *(const float4*)&As[k][ty * 4];
            float4 b4 = *(const float4*)&Ws[k][tx * 4];
            float av[4] = {a4.x, a4.y, a4.z, a4.w};
            float bv[4] = {b4.x, b4.y, b4.z, b4.w};
            #pragma unroll
            for (int i = 0; i < 4; i++)
                #pragma unroll
                for (int j = 0; j < 4; j++)
                    acc[i][j] = fmaf(av[i], bv[j], acc[i][j]);
        }
        __syncthreads();
    }
    #pragma unroll
    for (int i = 0; i < 4; i++) {
        int m = m0 + ty * 4 + i;
        float* crow = Cs + (size_t)m * SEQ + n0 + tx * 4;
        #pragma unroll
        for (int j = 0; j < 4; j++) crow[j] = acc[i][j];
    }
}

// ---------------- attention softmax (scale applied here) ----------------
__global__ __launch_bounds__(256) void attn_softmax_kernel() {
    size_t base = ((size_t)blockIdx.y * SEQ + blockIdx.x) * SEQ;
    float* row = g_scores + base;
    const float scale = 0.08838834764831845f;   // 1/sqrt(128)
    int tid = threadIdx.x;
    __shared__ float sm[8];

    float v[4];
    float mx = -1e30f;
    #pragma unroll
    for (int i = 0; i < 4; i++) { v[i] = row[tid + i * 256] * scale; mx = fmaxf(mx, v[i]); }
    mx = warp_max(mx);
    if ((tid & 31) == 0) sm[tid >> 5] = mx;
    __syncthreads();
    float bm = sm[0];
    #pragma unroll
    for (int i = 1; i < 8; i++) bm = fmaxf(bm, sm[i]);
    __syncthreads();

    float s = 0.f;
    #pragma unroll
    for (int i = 0; i < 4; i++) { v[i] = expf(v[i] - bm); s += v[i]; }
    s = warp_sum(s);
    if ((tid & 31) == 0) sm[tid >> 5] = s;
    __syncthreads();
    float tot = 0.f;
    #pragma unroll
    for (int i = 0; i < 8; i++) tot += sm[i];
    float inv = 1.f / tot;
    #pragma unroll
    for (int i = 0; i < 4; i++) row[tid + i * 256] = v[i] * inv;
}

// ---------------- attention AV: out = att @ V ----------------
__global__ __launch_bounds__(256) void attn_av_kernel() {
    int z = blockIdx.y; int b = z >> 2, h = z & 3;
    const float* V  = g_qkv + (size_t)b * SEQ * (3 * HS) + 2 * HS + h * HDIM;
    const float* Sc = g_scores + (size_t)z * SEQ * SEQ;
    int m0 = blockIdx.x * 64;

    __shared__ float As[32][64];     // [k][m]
    __shared__ float Vs[32][128];    // [k][d]
    int tid = threadIdx.x;
    int tx = tid & 15, ty = tid >> 4;
    float acc[4][8] = {};

    for (int kk = 0; kk < SEQ; kk += 32) {
        #pragma unroll
        for (int i = 0; i < 2; i++) {
            int f = tid + i * 256;
            int r = f >> 3, c = (f & 7) * 4;
            float4 a = *(const float4*)&Sc[(size_t)(m0 + r) * SEQ + kk + c];
            As[c + 0][r] = a.x; As[c + 1][r] = a.y; As[c + 2][r] = a.z; As[c + 3][r] = a.w;
        }
        #pragma unroll
        for (int i = 0; i < 4; i++) {
            int f = tid + i * 256;
            int k = f >> 5, c = (f & 31) * 4;
            *(float4*)&Vs[k][c] = *(const float4*)&V[(size_t)(kk + k) * (3 * HS) + c];
        }
        __syncthreads();
        #pragma unroll
        for (int k = 0; k < 32; k++) {
            float4 a4 = *(const float4*)&As[k][ty * 4];
            float4 v0 = *(const float4*)&Vs[k][tx * 8];
            float4 v1 = *(const float4*)&Vs[k][tx * 8 + 4];
            float av[4] = {a4.x, a4.y, a4.z, a4.w};
            float bv[8] = {v0.x, v0.y, v0.z, v0.w, v1.x, v1.y, v1.z, v1.w};
            #pragma unroll
            for (int i = 0; i < 4; i++)
                #pragma unroll
                for (int j = 0; j < 8; j++)
                    acc[i][j] = fmaf(av[i], bv[j], acc[i][j]);
        }
        __syncthreads();
    }
    #pragma unroll
    for (int i = 0; i < 4; i++) {
        int q = m0 + ty * 4 + i;
        float* orow = g_attno + (size_t)(b * SEQ + q) * HS + h * HDIM + tx * 8;
        #pragma unroll
        for (int j = 0; j < 8; j++) orow[j] = acc[i][j];
    }
}

// ---------------- fused residual-add + layernorm: O = LN(X + Y) ----------------
__global__ __launch_bounds__(128) void ln_add_kernel(
    const float* __restrict__ X, const float* __restrict__ Y,
    const float* __restrict__ gam, const float* __restrict__ bet,
    float* __restrict__ O)
{
    size_t base = (size_t)blockIdx.x * HS;
    int tid = threadIdx.x;
    __shared__ float sm[4];
    float v[4];
    #pragma unroll
    for (int i = 0; i < 4; i++) { int d = tid + i * 128; v[i] = X[base + d] + Y[base + d]; }
    float s = v[0] + v[1] + v[2] + v[3];
    s = warp_sum(s);
    if ((tid & 31) == 0) sm[tid >> 5] = s;
    __syncthreads();
    float mean = (sm[0] + sm[1] + sm[2] + sm[3]) * (1.f / HS);
    __syncthreads();
    float q = 0.f;
    #pragma unroll
    for (int i = 0; i < 4; i++) { float d = v[i] - mean; q += d * d; }
    q = warp_sum(q);
    if ((tid & 31) == 0) sm[tid >> 5] = q;
    __syncthreads();
    float var = (sm[0] + sm[1] + sm[2] + sm[3]) * (1.f / HS);
    float inv = rsqrtf(var + 1e-5f);
    #pragma unroll
    for (int i = 0; i < 4; i++) {
        int d = tid + i * 128;
        O[base + d] = (v[i] - mean) * inv * gam[d] + bet[d];
    }
}

// ---------------- specific-MoE router: softmax over 6, top-2, compact per expert ----------------
__global__ __launch_bounds__(256) void route_spec_kernel(const float* __restrict__ rw) {
    int warp = threadIdx.x >> 5, lane = threadIdx.x & 31;
    int token = blockIdx.x * 8 + warp;
    const float* hrow = g_h + (size_t)token * HS;
    float hv[16];
    #pragma unroll
    for (int j = 0; j < 16; j++) hv[j] = hrow[lane + j * 32];
    float logit[NE];
    #pragma unroll
    for (int e = 0; e < NE; e++) {
        const float* w = rw + e * HS;
        float p = 0.f;
        #pragma unroll
        for (int j = 0; j < 16; j++) p = fmaf(hv[j], w[lane + j * 32], p);
        logit[e] = warp_sum(p);
    }
    if (lane == 0) {
        float mx = logit[0];
        #pragma unroll
        for (int e = 1; e < NE; e++) mx = fmaxf(mx, logit[e]);
        float pr[NE], s = 0.f;
        #pragma unroll
        for (int e = 0; e < NE; e++) { pr[e] = expf(logit[e] - mx); s += pr[e]; }
        #pragma unroll
        for (int e = 0; e < NE; e++) pr[e] /= s;
        int i1 = 0;
        #pragma unroll
        for (int e = 1; e < NE; e++) if (pr[e] > pr[i1]) i1 = e;
        int i2 = (i1 == 0) ? 1 : 0;
        #pragma unroll
        for (int e = 0; e < NE; e++) if (e != i1 && pr[e] > pr[i2]) i2 = e;
        float den = pr[i1] + pr[i2] + 1e-9f;
        float w1 = pr[i1] / den, w2 = pr[i2] / den;
        int p1 = atomicAdd(&g_ecnt[i1], 1);
        g_eidx[i1 * NT + p1] = token; g_ewt[i1 * NT + p1] = w1;
        int p2 = atomicAdd(&g_ecnt[i2], 1);
        g_eidx[i2 * NT + p2] = token; g_ewt[i2 * NT + p2] = w2;
    }
}

// ---------------- shared-MoE router: softmax over 2 ----------------
__global__ __launch_bounds__(256) void route_shared_kernel(const float* __restrict__ rw) {
    int warp = threadIdx.x >> 5, lane = threadIdx.x & 31;
    int token = blockIdx.x * 8 + warp;
    const float* hrow = g_h + (size_t)token * HS;
    float hv[16];
    #pragma unroll
    for (int j = 0; j < 16; j++) hv[j] = hrow[lane + j * 32];
    float logit[NS];
    #pragma unroll
    for (int e = 0; e < NS; e++) {
        const float* w = rw + e * HS;
        float p = 0.f;
        #pragma unroll
        for (int j = 0; j < 16; j++) p = fmaf(hv[j], w[lane + j * 32], p);
        logit[e] = warp_sum(p);
    }
    if (lane == 0) {
        float mx = fmaxf(logit[0], logit[1]);
        float e0 = expf(logit[0] - mx), e1 = expf(logit[1] - mx);
        float inv = 1.f / (e0 + e1);
        g_sp[token * NS + 0] = e0 * inv;
        g_sp[token * NS + 1] = e1 * inv;
    }
}

// ---------------- mean pool over sequence ----------------
__global__ void pool_mean_kernel() {
    int b = blockIdx.x, d = threadIdx.x;  // 512 threads
    float s = 0.f;
    for (int t = 0; t < SEQ; t++) s += g_h[((size_t)b * SEQ + t) * HS + d];
    g_pool[b * HS + d] = s * (1.f / SEQ);
}

// ---------------- classifier head ----------------
__global__ __launch_bounds__(128) void cls_head_kernel(
    const float* __restrict__ w, const float* __restrict__ bias, float* __restrict__ out)
{
    int n = blockIdx.x, b = blockIdx.y;
    int tid = threadIdx.x;
    __shared__ float sm[4];
    float p = 0.f;
    for (int j = tid; j < HS; j += 128) p = fmaf(g_pool[b * HS + j], w[n * HS + j], p);
    p = warp_sum(p);
    if ((tid & 31) == 0) sm[tid >> 5] = p;
    __syncthreads();
    if (tid == 0) out[b * NCLS + n] = sm[0] + sm[1] + sm[2] + sm[3] + bias[n];
}

// ---------------- host-side launch helpers ----------------
static void launch_gemm(int act, const float* A, const float* W, const float* bias,
                        float* C, int M, int N, int K,
                        const int* gidx = nullptr, const int* mcnt = nullptr)
{
    dim3 grid(N / 64, (M + 63) / 64);
    if (act == 0)      gemm_tn<0, 0><<<grid, 256>>>(A, W, bias, C, M, N, K, gidx, mcnt, nullptr, nullptr, 0);
    else if (act == 1) gemm_tn<1, 0><<<grid, 256>>>(A, W, bias, C, M, N, K, gidx, mcnt, nullptr, nullptr, 0);
    else               gemm_tn<2, 0><<<grid, 256>>>(A, W, bias, C, M, N, K, gidx, mcnt, nullptr, nullptr, 0);
}

static void launch_gemm_scatter(const float* A, const float* W, const float* bias,
                                float* C, int M, int N, int K,
                                const int* mcnt, const int* sidx,
                                const float* wv, int ws)
{
    dim3 grid(N / 64, (M + 63) / 64);
    gemm_tn<0, 1><<<grid, 256>>>(A, W, bias, C, M, N, K, nullptr, mcnt, sidx, wv, ws);
}

extern "C" void kernel_launch(void* const* d_in, const int* in_sizes, int n_in,
                              void* d_out, int out_size)
{
    const float* x         = (const float*)d_in[0];
    const float* tok_w1    = (const float*)d_in[1];
    const float* tok_b1    = (const float*)d_in[2];
    const float* tok_w2    = (const float*)d_in[3];
    const float* tok_b2    = (const float*)d_in[4];
    const float* proj_w    = (const float*)d_in[5];
    const float* proj_b    = (const float*)d_in[6];
    const float* attn_wqkv = (const float*)d_in[7];
    const float* attn_bqkv = (const float*)d_in[8];
    const float* attn_wo   = (const float*)d_in[9];
    const float* attn_bo   = (const float*)d_in[10];
    const float* ln1_g     = (const float*)d_in[11];
    const float* ln1_b     = (const float*)d_in[12];
    const float* spec_rw   = (const float*)d_in[13];
    const float* spec_f1w  = (const float*)d_in[14];
    const float* spec_f1b  = (const float*)d_in[15];
    const float* spec_f2w  = (const float*)d_in[16];
    const float* spec_f2b  = (const float*)d_in[17];
    const float* shr_rw    = (const float*)d_in[18];
    const float* shr_f1w   = (const float*)d_in[19];
    const float* shr_f1b   = (const float*)d_in[20];
    const float* shr_f2w   = (const float*)d_in[21];
    const float* shr_f2b   = (const float*)d_in[22];
    const float* lnm_g     = (const float*)d_in[23];
    const float* lnm_b     = (const float*)d_in[24];
    const float* ln2_g     = (const float*)d_in[25];
    const float* ln2_b     = (const float*)d_in[26];
    const float* cls_w     = (const float*)d_in[27];
    const float* cls_b     = (const float*)d_in[28];
    float* out = (float*)d_out;

    float *pt, *pz1, *pz, *ph, *pattno, *pa, *pspec, *pm, *phid, *psp, *pewt;
    int *peidx, *pecnt;
    cudaGetSymbolAddress((void**)&pt, g_t);
    cudaGetSymbolAddress((void**)&pz1, g_z1);
    cudaGetSymbolAddress((void**)&pz, g_z);
    cudaGetSymbolAddress((void**)&ph, g_h);
    float* pqkv; cudaGetSymbolAddress((void**)&pqkv, g_qkv);
    cudaGetSymbolAddress((void**)&pattno, g_attno);
    cudaGetSymbolAddress((void**)&pa, g_a);
    cudaGetSymbolAddress((void**)&pspec, g_spec);
    cudaGetSymbolAddress((void**)&pm, g_m);
    cudaGetSymbolAddress((void**)&phid, g_hid);
    cudaGetSymbolAddress((void**)&psp, g_sp);
    cudaGetSymbolAddress((void**)&pewt, g_ewt);
    cudaGetSymbolAddress((void**)&peidx, g_eidx);
    cudaGetSymbolAddress((void**)&pecnt, g_ecnt);

    // ---- tokenizer + projection ----
    patchify_kernel<<<(NT * PD + 255) / 256, 256>>>(x);
    launch_gemm(1, pt,  tok_w1, tok_b1, pz1, NT, SF, PD);
    launch_gemm(1, pz1, tok_w2, tok_b2, pz,  NT, ED, SF);
    add_pe_kernel<<<(NT * ED + 255) / 256, 256>>>();
    launch_gemm(0, pz,  proj_w, proj_b, ph,  NT, HS, ED);

    // ---- transformer layers ----
    for (int l = 0; l < NLAY; l++) {
        // attention
        launch_gemm(0, ph, attn_wqkv + (size_t)l * 3 * HS * HS, attn_bqkv + (size_t)l * 3 * HS,
                    pqkv, NT, 3 * HS, HS);
        attn_scores_kernel<<<dim3(SEQ / 64, SEQ / 64, NB * NHD), 256>>>();
        attn_softmax_kernel<<<dim3(SEQ, NB * NHD), 256>>>();
        attn_av_kernel<<<dim3(SEQ / 64, NB * NHD), 256>>>();
        launch_gemm(0, pattno, attn_wo + (size_t)l * HS * HS, attn_bo + (size_t)l * HS,
                    pa, NT, HS, HS);
        ln_add_kernel<<<NT, 128>>>(ph, pa, ln1_g + l * HS, ln1_b + l * HS, ph);

        // MoE
        cudaMemsetAsync(pecnt, 0, NE * sizeof(int));
        cudaMemsetAsync(pspec, 0, (size_t)NT * HS * sizeof(float));
        route_spec_kernel<<<NT / 8, 256>>>(spec_rw + (size_t)l * NE * HS);
        for (int e = 0; e < NE; e++) {
            const float* f1w = spec_f1w + (size_t)(l * NE + e) * FF * HS;
            const float* f1b = spec_f1b + (size_t)(l * NE + e) * FF;
            const float* f2w = spec_f2w + (size_t)(l * NE + e) * HS * FF;
            const float* f2b = spec_f2b + (size_t)(l * NE + e) * HS;
            launch_gemm(2, ph, f1w, f1b, phid, NT, FF, HS, peidx + e * NT, pecnt + e);
            launch_gemm_scatter(phid, f2w, f2b, pspec, NT, HS, FF,
                                pecnt + e, peidx + e * NT, pewt + e * NT, 1);
        }
        route_shared_kernel<<<NT / 8, 256>>>(shr_rw + (size_t)l * NS * HS);
        for (int e = 0; e < NS; e++) {
            const float* f1w = shr_f1w + (size_t)(l * NS + e) * FF * HS;
            const float* f1b = shr_f1b + (size_t)(l * NS + e) * FF;
            const float* f2w = shr_f2w + (size_t)(l * NS + e) * HS * FF;
            const float* f2b = shr_f2b + (size_t)(l * NS + e) * HS;
            launch_gemm(2, ph, f1w, f1b, phid, NT, FF, HS);
            launch_gemm_scatter(phid, f2w, f2b, pspec, NT, HS, FF,
                                nullptr, nullptr, psp + e, NS);
        }
        ln_add_kernel<<<NT, 128>>>(ph, pspec, lnm_g + l * HS, lnm_b + l * HS, pm);
        ln_add_kernel<<<NT, 128>>>(ph, pm, ln2_g + l * HS, ln2_b + l * HS, ph);
    }

    // ---- head ----
    pool_mean_kernel<<<NB, HS>>>();
    cls_head_kernel<<<dim3(NCLS, NB), 128>>>(cls_w, cls_b, out);
}

// round 2
// speedup vs baseline: 1.0001x; 1.0001x over previous
#include <cuda_runtime.h>
#include <math.h>

// ---------------- problem constants ----------------
#define NB    16          // batch
#define NCH   5           // channels
#define HIMG  256
#define WIMG  256
#define PP    8           // patch
#define SEQ   1024        // tokens per image (32*32)
#define NT    16384       // total tokens NB*SEQ
#define PD    320         // C*P*P
#define SF    64
#define ED    128
#define HS    512
#define NHD   4
#define HDIM  128
#define FF    2048
#define NE    6
#define NS    2
#define NLAY  4
#define NCLS  2

// ---------------- scratch (static device memory; no allocation allowed) ----------------
__device__ float g_t[NT * PD];
__device__ float g_z1[NT * SF];
__device__ float g_z[NT * ED];
__device__ float g_h[NT * HS];
__device__ float g_qkv[NT * 3 * HS];
__device__ float g_scores[(size_t)NB * NHD * SEQ * SEQ];   // 268 MB
__device__ float g_attno[NT * HS];
__device__ float g_a[NT * HS];
__device__ float g_spec[NT * HS];
__device__ float g_m[NT * HS];
__device__ float g_hid[NT * FF];                            // 134 MB
__device__ float g_sp[NT * NS];
__device__ int   g_eidx[NE * NT];
__device__ float g_ewt[NE * NT];
__device__ int   g_ecnt[NE];
__device__ float g_pool[NB * HS];

// ---------------- small helpers ----------------
__device__ __forceinline__ float warp_sum(float v) {
    #pragma unroll
    for (int o = 16; o; o >>= 1) v += __shfl_xor_sync(0xffffffffu, v, o);
    return v;
}
__device__ __forceinline__ float warp_max(float v) {
    #pragma unroll
    for (int o = 16; o; o >>= 1) v = fmaxf(v, __shfl_xor_sync(0xffffffffu, v, o));
    return v;
}

// ---------------- patch extraction ----------------
__global__ void patchify_kernel(const float* __restrict__ x) {
    int idx = blockIdx.x * blockDim.x + threadIdx.x;
    if (idx >= NT * PD) return;
    int n = idx / PD, f = idx % PD;
    int b = n / SEQ, s = n % SEQ;
    int sh = s >> 5, sw = s & 31;
    int c = f >> 6, r = f & 63;
    int pi = r >> 3, pj = r & 7;
    g_t[idx] = x[(((size_t)(b * NCH + c) * HIMG + (sh * PP + pi)) * WIMG) + (sw * PP + pj)];
}

// ---------------- positional encoding add ----------------
__global__ void add_pe_kernel() {
    int idx = blockIdx.x * blockDim.x + threadIdx.x;
    if (idx >= NT * ED) return;
    int n = idx >> 7, d = idx & 127;
    int s = n & (SEQ - 1);
    int i2 = d & ~1;
    float div = expf(-(float)i2 * (9.2103403719761836f / (float)ED));
    float arg = (float)s * div;
    float pe = (d & 1) ? cosf(arg) : sinf(arg);
    g_z[idx] += pe;
}

// ---------------- generic TN GEMM:  C[m,n] = act( sum_k A[m,k]*W[n,k] + bias[n] ) ----------------
// BM=BN=64, BK=32, 256 threads, 4x4 microtile.
// gidx: optional row gather on A. mcnt: optional dynamic row count (device).
// SCATTER: C[sidx[m]] += wv[m*ws] * (acc + bias[n])   (row-unique within a launch)
template<int ACT, int SCATTER>
__global__ __launch_bounds__(256) void gemm_tn(
    const float* __restrict__ A, const float* __restrict__ W,
    const float* __restrict__ bias, float* __restrict__ C,
    int M, int N, int K,
    const int* __restrict__ gidx, const int* __restrict__ mcnt,
    const int* __restrict__ sidx, const float* __restrict__ wv, int ws)
{
    int Mr = mcnt ? *mcnt : M;
    int m0 = blockIdx.y * 64;
    int n0 = blockIdx.x * 64;
    if (m0 >= Mr) return;

    __shared__ float As[32][64];
    __shared__ float Ws[32][64];
    __shared__ int   ridx[64];

    int tid = threadIdx.x;
    int tx = tid & 15, ty = tid >> 4;

    if (tid < 64) {
        int r = m0 + tid;
        if (r > Mr - 1) r = Mr - 1;
        ridx[tid] = gidx ? gidx[r] : r;
    }
    __syncthreads();

    float acc[4][4] = {};

    for (int kk = 0; kk < K; kk += 32) {
        #pragma unroll
        for (int i = 0; i < 2; i++) {
            int f = tid + i * 256;
            int r = f >> 3, c = (f & 7) * 4;
            float4 av = *(const float4*)&A[(size_t)ridx[r] * K + kk + c];
            As[c + 0][r] = av.x; As[c + 1][r] = av.y; As[c + 2][r] = av.z; As[c + 3][r] = av.w;
            float4 wv4 = *(const float4*)&W[(size_t)(n0 + r) * K + kk + c];
            Ws[c + 0][r] = wv4.x; Ws[c + 1][r] = wv4.y; Ws[c + 2][r] = wv4.z; Ws[c + 3][r] = wv4.w;
        }
        __syncthreads();
        #pragma unroll
        for (int k = 0; k < 32; k++) {
            float4 a4 = *(const float4*)&As[k][ty * 4];
            float4 b4 = *(const float4*)&Ws[k][tx * 4];
            float av[4] = {a4.x, a4.y, a4.z, a4.w};
            float bv[4] = {b4.x, b4.y, b4.z, b4.w};
            #pragma unroll
            for (int i = 0; i < 4; i++)
                #pragma unroll
                for (int j = 0; j < 4; j++)
                    acc[i][j] = fmaf(av[i], bv[j], acc[i][j]);
        }
        __syncthreads();
    }

    #pragma unroll
    for (int i = 0; i < 4; i++) {
        int m = m0 + ty * 4 + i;
        if (m >= Mr) break;
        if (SCATTER) {
            int row = sidx ? sidx[m] : m;
            float wgt = wv[(size_t)m * ws];
            float* crow = C + (size_t)row * N + n0 + tx * 4;
            #pragma unroll
            for (int j = 0; j < 4; j++) {
                int n = n0 + tx * 4 + j;
                crow[j] += wgt * (acc[i][j] + bias[n]);
            }
        } else {
            float* crow = C + (size_t)m * N + n0 + tx * 4;
            #pragma unroll
            for (int j = 0; j < 4; j++) {
                int n = n0 + tx * 4 + j;
                float v = acc[i][j] + bias[n];
                if (ACT == 1) v = fmaxf(v, 0.f);
                if (ACT == 2) v = 0.5f * v * (1.f + erff(v * 0.70710678118654752f));
                crow[j] = v;
            }
        }
    }
}

// ---------------- attention: scores = Q @ K^T (raw; scale applied in softmax) ----------------
__global__ __launch_bounds__(256) void attn_scores_kernel() {
    int z = blockIdx.z; int b = z >> 2; int h = z & 3;
    const float* Q  = g_qkv + (size_t)b * SEQ * (3 * HS) + h * HDIM;
    const float* Kp = Q + HS;
    float* Cs = g_scores + (size_t)z * SEQ * SEQ;
    int m0 = blockIdx.y * 64, n0 = blockIdx.x * 64;

    __shared__ float As[32][64];
    __shared__ float Ws[32][64];
    int tid = threadIdx.x;
    int tx = tid & 15, ty = tid >> 4;
    float acc[4][4] = {};

    for (int kk = 0; kk < HDIM; kk += 32) {
        #pragma unroll
        for (int i = 0; i < 2; i++) {
            int f = tid + i * 256;
            int r = f >> 3, c = (f & 7) * 4;
            float4 qa = *(const float4*)&Q[(size_t)(m0 + r) * (3 * HS) + kk + c];
            As[c + 0][r] = qa.x; As[c + 1][r] = qa.y; As[c + 2][r] = qa.z; As[c + 3][r] = qa.w;
            float4 ka = *(const float4*)&Kp[(size_t)(n0 + r) * (3 * HS) + kk + c];
            Ws[c + 0][r] = ka.x; Ws[c + 1][r] = ka.y; Ws[c + 2][r] = ka.z; Ws[c + 3][r] = ka.w;
        }
        __syncthreads();
        #pragma unroll
        for (int k = 0; k < 32; k++) {
            float4 a4 = *(const float4*)&As[k][ty * 4];
            float4 b4 = *(const float4*)&Ws[k][tx * 4];
            float av[4] = {a4.x, a4.y, a4.z, a4.w};
            float bv[4] = {b4.x, b4.y, b4.z, b4.w};
            #pragma unroll
            for (int i = 0; i < 4; i++)
                #pragma unroll
                for (int j = 0; j < 4; j++)
                    acc[i][j] = fmaf(av[i], bv[j], acc[i][j]);
        }
        __syncthreads();
    }
    #pragma unroll
    for (int i = 0; i < 4; i++) {
        int m = m0 + ty * 4 + i;
        float* crow = Cs + (size_t)m * SEQ + n0 + tx * 4;
        #pragma unroll
        for (int j = 0; j < 4; j++) crow[j] = acc[i][j];
    }
}

// ---------------- attention softmax (scale applied here) ----------------
__global__ __launch_bounds__(256) void attn_softmax_kernel() {
    size_t base = ((size_t)blockIdx.y * SEQ + blockIdx.x) * SEQ;
    float* row = g_scores + base;
    const float scale = 0.08838834764831845f;   // 1/sqrt(128)
    int tid = threadIdx.x;
    __shared__ float sm[8];

    float v[4];
    float mx = -1e30f;
    #pragma unroll
    for (int i = 0; i < 4; i++) { v[i] = row[tid + i * 256] * scale; mx = fmaxf(mx, v[i]); }
    mx = warp_max(mx);
    if ((tid & 31) == 0) sm[tid >> 5] = mx;
    __syncthreads();
    float bm = sm[0];
    #pragma unroll
    for (int i = 1; i < 8; i++) bm = fmaxf(bm, sm[i]);
    __syncthreads();

    float s = 0.f;
    #pragma unroll
    for (int i = 0; i < 4; i++) { v[i] = expf(v[i] - bm); s += v[i]; }
    s = warp_sum(s);
    if ((tid & 31) == 0) sm[tid >> 5] = s;
    __syncthreads();
    float tot = 0.f;
    #pragma unroll
    for (int i = 0; i < 8; i++) tot += sm[i];
    float inv = 1.f / tot;
    #pragma unroll
    for (int i = 0; i < 4; i++) row[tid + i * 256] = v[i] * inv;
}

// ---------------- attention AV: out = att @ V ----------------
__global__ __launch_bounds__(256) void attn_av_kernel() {
    int z = blockIdx.y; int b = z >> 2, h = z & 3;
    const float* V  = g_qkv + (size_t)b * SEQ * (3 * HS) + 2 * HS + h * HDIM;
    const float* Sc = g_scores + (size_t)z * SEQ * SEQ;
    int m0 = blockIdx.x * 64;

    __shared__ float As[32][64];     // [k][m]
    __shared__ float Vs[32][128];    // [k][d]
    int tid = threadIdx.x;
    int tx = tid & 15, ty = tid >> 4;
    float acc[4][8] = {};

    for (int kk = 0; kk < SEQ; kk += 32) {
        #pragma unroll
        for (int i = 0; i < 2; i++) {
            int f = tid + i * 256;
            int r = f >> 3, c = (f & 7) * 4;
            float4 a = *(const float4*)&Sc[(size_t)(m0 + r) * SEQ + kk + c];
            As[c + 0][r] = a.x; As[c + 1][r] = a.y; As[c + 2][r] = a.z; As[c + 3][r] = a.w;
        }
        #pragma unroll
        for (int i = 0; i < 4; i++) {
            int f = tid + i * 256;
            int k = f >> 5, c = (f & 31) * 4;
            *(float4*)&Vs[k][c] = *(const float4*)&V[(size_t)(kk + k) * (3 * HS) + c];
        }
        __syncthreads();
        #pragma unroll
        for (int k = 0; k < 32; k++) {
            float4 a4 = *(const float4*)&As[k][ty * 4];
            float4 v0 = *(const float4*)&Vs[k][tx * 8];
            float4 v1 = *(const float4*)&Vs[k][tx * 8 + 4];
            float av[4] = {a4.x, a4.y, a4.z, a4.w};
            float bv[8] = {v0.x, v0.y, v0.z, v0.w, v1.x, v1.y, v1.z, v1.w};
            #pragma unroll
            for (int i = 0; i < 4; i++)
                #pragma unroll
                for (int j = 0; j < 8; j++)
                    acc[i][j] = fmaf(av[i], bv[j], acc[i][j]);
        }
        __syncthreads();
    }
    #pragma unroll
    for (int i = 0; i < 4; i++) {
        int q = m0 + ty * 4 + i;
        float* orow = g_attno + (size_t)(b * SEQ + q) * HS + h * HDIM + tx * 8;
        #pragma unroll
        for (int j = 0; j < 8; j++) orow[j] = acc[i][j];
    }
}

// ---------------- fused residual-add + layernorm: O = LN(X + Y) ----------------
__global__ __launch_bounds__(128) void ln_add_kernel(
    const float* __restrict__ X, const float* __restrict__ Y,
    const float* __restrict__ gam, const float* __restrict__ bet,
    float* __restrict__ O)
{
    size_t base = (size_t)blockIdx.x * HS;
    int tid = threadIdx.x;
    __shared__ float sm[4];
    float v[4];
    #pragma unroll
    for (int i = 0; i < 4; i++) { int d = tid + i * 128; v[i] = X[base + d] + Y[base + d]; }
    float s = v[0] + v[1] + v[2] + v[3];
    s = warp_sum(s);
    if ((tid & 31) == 0) sm[tid >> 5] = s;
    __syncthreads();
    float mean = (sm[0] + sm[1] + sm[2] + sm[3]) * (1.f / HS);
    __syncthreads();
    float q = 0.f;
    #pragma unroll
    for (int i = 0; i < 4; i++) { float d = v[i] - mean; q += d * d; }
    q = warp_sum(q);
    if ((tid & 31) == 0) sm[tid >> 5] = q;
    __syncthreads();
    float var = (sm[0] + sm[1] + sm[2] + sm[3]) * (1.f / HS);
    float inv = rsqrtf(var + 1e-5f);
    #pragma unroll
    for (int i = 0; i < 4; i++) {
        int d = tid + i * 128;
        O[base + d] = (v[i] - mean) * inv * gam[d] + bet[d];
    }
}

// ---------------- specific-MoE router: softmax over 6, top-2, compact per expert ----------------
__global__ __launch_bounds__(256) void route_spec_kernel(const float* __restrict__ rw) {
    int warp = threadIdx.x >> 5, lane = threadIdx.x & 31;
    int token = blockIdx.x * 8 + warp;
    const float* hrow = g_h + (size_t)token * HS;
    float hv[16];
    #pragma unroll
    for (int j = 0; j < 16; j++) hv[j] = hrow[lane + j * 32];
    float logit[NE];
    #pragma unroll
    for (int e = 0; e < NE; e++) {
        const float* w = rw + e * HS;
        float p = 0.f;
        #pragma unroll
        for (int j = 0; j < 16; j++) p = fmaf(hv[j], w[lane + j * 32], p);
        logit[e] = warp_sum(p);
    }
    if (lane == 0) {
        float mx = logit[0];
        #pragma unroll
        for (int e = 1; e < NE; e++) mx = fmaxf(mx, logit[e]);
        float pr[NE], s = 0.f;
        #pragma unroll
        for (int e = 0; e < NE; e++) { pr[e] = expf(logit[e] - mx); s += pr[e]; }
        #pragma unroll
        for (int e = 0; e < NE; e++) pr[e] /= s;
        int i1 = 0;
        #pragma unroll
        for (int e = 1; e < NE; e++) if (pr[e] > pr[i1]) i1 = e;
        int i2 = (i1 == 0) ? 1 : 0;
        #pragma unroll
        for (int e = 0; e < NE; e++) if (e != i1 && pr[e] > pr[i2]) i2 = e;
        float den = pr[i1] + pr[i2] + 1e-9f;
        float w1 = pr[i1] / den, w2 = pr[i2] / den;
        int p1 = atomicAdd(&g_ecnt[i1], 1);
        g_eidx[i1 * NT + p1] = token; g_ewt[i1 * NT + p1] = w1;
        int p2 = atomicAdd(&g_ecnt[i2], 1);
        g_eidx[i2 * NT + p2] = token; g_ewt[i2 * NT + p2] = w2;
    }
}

// ---------------- shared-MoE router: softmax over 2 ----------------
__global__ __launch_bounds__(256) void route_shared_kernel(const float* __restrict__ rw) {
    int warp = threadIdx.x >> 5, lane = threadIdx.x & 31;
    int token = blockIdx.x * 8 + warp;
    const float* hrow = g_h + (size_t)token * HS;
    float hv[16];
    #pragma unroll
    for (int j = 0; j < 16; j++) hv[j] = hrow[lane + j * 32];
    float logit[NS];
    #pragma unroll
    for (int e = 0; e < NS; e++) {
        const float* w = rw + e * HS;
        float p = 0.f;
        #pragma unroll
        for (int j = 0; j < 16; j++) p = fmaf(hv[j], w[lane + j * 32], p);
        logit[e] = warp_sum(p);
    }
    if (lane == 0) {
        float mx = fmaxf(logit[0], logit[1]);
        float e0 = expf(logit[0] - mx), e1 = expf(logit[1] - mx);
        float inv = 1.f / (e0 + e1);
        g_sp[token * NS + 0] = e0 * inv;
        g_sp[token * NS + 1] = e1 * inv;
    }
}

// ---------------- mean pool over sequence ----------------
__global__ void pool_mean_kernel() {
    int b = blockIdx.x, d = threadIdx.x;  // 512 threads
    float s = 0.f;
    for (int t = 0; t < SEQ; t++) s += g_h[((size_t)b * SEQ + t) * HS + d];
    g_pool[b * HS + d] = s * (1.f / SEQ);
}

// ---------------- classifier head ----------------
__global__ __launch_bounds__(128) void cls_head_kernel(
    const float* __restrict__ w, const float* __restrict__ bias, float* __restrict__ out)
{
    int n = blockIdx.x, b = blockIdx.y;
    int tid = threadIdx.x;
    __shared__ float sm[4];
    float p = 0.f;
    for (int j = tid; j < HS; j += 128) p = fmaf(g_pool[b * HS + j], w[n * HS + j], p);
    p = warp_sum(p);
    if ((tid & 31) == 0) sm[tid >> 5] = p;
    __syncthreads();
    if (tid == 0) out[b * NCLS + n] = sm[0] + sm[1] + sm[2] + sm[3] + bias[n];
}

// ---------------- host-side launch helpers ----------------
static void launch_gemm(int act, const float* A, const float* W, const float* bias,
                        float* C, int M, int N, int K,
                        const int* gidx = nullptr, const int* mcnt = nullptr)
{
    dim3 grid(N / 64, (M + 63) / 64);
    if (act == 0)      gemm_tn<0, 0><<<grid, 256>>>(A, W, bias, C, M, N, K, gidx, mcnt, nullptr, nullptr, 0);
    else if (act == 1) gemm_tn<1, 0><<<grid, 256>>>(A, W, bias, C, M, N, K, gidx, mcnt, nullptr, nullptr, 0);
    else               gemm_tn<2, 0><<<grid, 256>>>(A, W, bias, C, M, N, K, gidx, mcnt, nullptr, nullptr, 0);
}

static void launch_gemm_scatter(const float* A, const float* W, const float* bias,
                                float* C, int M, int N, int K,
                                const int* mcnt, const int* sidx,
                                const float* wv, int ws)
{
    dim3 grid(N / 64, (M + 63) / 64);
    gemm_tn<0, 1><<<grid, 256>>>(A, W, bias, C, M, N, K, nullptr, mcnt, sidx, wv, ws);
}

extern "C" void kernel_launch(void* const* d_in, const int* in_sizes, int n_in,
                              void* d_out, int out_size)
{
    const float* x         = (const float*)d_in[0];
    const float* tok_w1    = (const float*)d_in[1];
    const float* tok_b1    = (const float*)d_in[2];
    const float* tok_w2    = (const float*)d_in[3];
    const float* tok_b2    = (const float*)d_in[4];
    const float* proj_w    = (const float*)d_in[5];
    const float* proj_b    = (const float*)d_in[6];
    const float* attn_wqkv = (const float*)d_in[7];
    const float* attn_bqkv = (const float*)d_in[8];
    const float* attn_wo   = (const float*)d_in[9];
    const float* attn_bo   = (const float*)d_in[10];
    const float* ln1_g     = (const float*)d_in[11];
    const float* ln1_b     = (const float*)d_in[12];
    const float* spec_rw   = (const float*)d_in[13];
    const float* spec_f1w  = (const float*)d_in[14];
    const float* spec_f1b  = (const float*)d_in[15];
    const float* spec_f2w  = (const float*)d_in[16];
    const float* spec_f2b  = (const float*)d_in[17];
    const float* shr_rw    = (const float*)d_in[18];
    const float* shr_f1w   = (const float*)d_in[19];
    const float* shr_f1b   = (const float*)d_in[20];
    const float* shr_f2w   = (const float*)d_in[21];
    const float* shr_f2b   = (const float*)d_in[22];
    const float* lnm_g     = (const float*)d_in[23];
    const float* lnm_b     = (const float*)d_in[24];
    const float* ln2_g     = (const float*)d_in[25];
    const float* ln2_b     = (const float*)d_in[26];
    const float* cls_w     = (const float*)d_in[27];
    const float* cls_b     = (const float*)d_in[28];
    float* out = (float*)d_out;

    float *pt, *pz1, *pz, *ph, *pattno, *pa, *pspec, *pm, *phid, *psp, *pewt;
    int *peidx, *pecnt;
    cudaGetSymbolAddress((void**)&pt, g_t);
    cudaGetSymbolAddress((void**)&pz1, g_z1);
    cudaGetSymbolAddress((void**)&pz, g_z);
    cudaGetSymbolAddress((void**)&ph, g_h);
    float* pqkv; cudaGetSymbolAddress((void**)&pqkv, g_qkv);
    cudaGetSymbolAddress((void**)&pattno, g_attno);
    cudaGetSymbolAddress((void**)&pa, g_a);
    cudaGetSymbolAddress((void**)&pspec, g_spec);
    cudaGetSymbolAddress((void**)&pm, g_m);
    cudaGetSymbolAddress((void**)&phid, g_hid);
    cudaGetSymbolAddress((void**)&psp, g_sp);
    cudaGetSymbolAddress((void**)&pewt, g_ewt);
    cudaGetSymbolAddress((void**)&peidx, g_eidx);
    cudaGetSymbolAddress((void**)&pecnt, g_ecnt);

    // ---- tokenizer + projection ----
    patchify_kernel<<<(NT * PD + 255) / 256, 256>>>(x);
    launch_gemm(1, pt,  tok_w1, tok_b1, pz1, NT, SF, PD);
    launch_gemm(1, pz1, tok_w2, tok_b2, pz,  NT, ED, SF);
    add_pe_kernel<<<(NT * ED + 255) / 256, 256>>>();
    launch_gemm(0, pz,  proj_w, proj_b, ph,  NT, HS, ED);

    // ---- transformer layers ----
    for (int l = 0; l < NLAY; l++) {
        // attention
        launch_gemm(0, ph, attn_wqkv + (size_t)l * 3 * HS * HS, attn_bqkv + (size_t)l * 3 * HS,
                    pqkv, NT, 3 * HS, HS);
        attn_scores_kernel<<<dim3(SEQ / 64, SEQ / 64, NB * NHD), 256>>>();
        attn_softmax_kernel<<<dim3(SEQ, NB * NHD), 256>>>();
        attn_av_kernel<<<dim3(SEQ / 64, NB * NHD), 256>>>();
        launch_gemm(0, pattno, attn_wo + (size_t)l * HS * HS, attn_bo + (size_t)l * HS,
                    pa, NT, HS, HS);
        ln_add_kernel<<<NT, 128>>>(ph, pa, ln1_g + l * HS, ln1_b + l * HS, ph);

        // MoE
        cudaMemsetAsync(pecnt, 0, NE * sizeof(int));
        cudaMemsetAsync(pspec, 0, (size_t)NT * HS * sizeof(float));
        route_spec_kernel<<<NT / 8, 256>>>(spec_rw + (size_t)l * NE * HS);
        for (int e = 0; e < NE; e++) {
            const float* f1w = spec_f1w + (size_t)(l * NE + e) * FF * HS;
            const float* f1b = spec_f1b + (size_t)(l * NE + e) * FF;
            const float* f2w = spec_f2w + (size_t)(l * NE + e) * HS * FF;
            const float* f2b = spec_f2b + (size_t)(l * NE + e) * HS;
            launch_gemm(2, ph, f1w, f1b, phid, NT, FF, HS, peidx + e * NT, pecnt + e);
            launch_gemm_scatter(phid, f2w, f2b, pspec, NT, HS, FF,
                                pecnt + e, peidx + e * NT, pewt + e * NT, 1);
        }
        route_shared_kernel<<<NT / 8, 256>>>(shr_rw + (size_t)l * NS * HS);
        for (int e = 0; e < NS; e++) {
            const float* f1w = shr_f1w + (size_t)(l * NS + e) * FF * HS;
            const float* f1b = shr_f1b + (size_t)(l * NS + e) * FF;
            const float* f2w = shr_f2w + (size_t)(l * NS + e) * HS * FF;
            const float* f2b = shr_f2b + (size_t)(l * NS + e) * HS;
            launch_gemm(2, ph, f1w, f1b, phid, NT, FF, HS);
            launch_gemm_scatter(phid, f2w, f2b, pspec, NT, HS, FF,
                                nullptr, nullptr, psp + e, NS);
        }
        ln_add_kernel<<<NT, 128>>>(ph, pspec, lnm_g + l * HS, lnm_b + l * HS, pm);
        ln_add_kernel<<<NT, 128>>>(ph, pm, ln2_g + l * HS, ln2_b + l * HS, ph);
    }

    // ---- head ----
    pool_mean_kernel<<<NB, HS>>>();
    cls_head_kernel<<<dim3(NCLS, NB), 128>>>(cls_w, cls_b, out);
}